// round 14
// baseline (speedup 1.0000x reference)
#include <cuda_runtime.h>
#include <cuda_fp16.h>
#include <cstdint>

// Problem dims (fixed by the dataset)
#define NB   8192   // batch
#define KCIN 512    // in_channels
#define HD   2048   // hidden
#define HD2  4096   // 2*hidden

// -------- scratch (device globals: allocation-free rule) --------
__device__ float  g_comb[NB * HD];            // 67 MB: xp (fp32, GEMM1 out / LN in)
__device__ __half g_combh[(size_t)NB * HD2];  // 67 MB: fp16 tanh(LN(concat))
__device__ __half g_wh[(size_t)8192 * HD2];   // 67 MB: fp16 fused W_all [8192,4096]
__device__ __half g_xh[(size_t)NB * KCIN];    // 8 MB:  fp16 x
__device__ __half g_wph[(size_t)HD * KCIN];   // 2 MB:  fp16 W_proj
__device__ __half g_gates[4LL * NB * HD];     // 134 MB: f,i,c2,o pre-activations (fp16)

// ================= small helpers =================
__device__ __forceinline__ uint32_t smem_u32(const void* p) {
    uint32_t a;
    asm("{ .reg .u64 t; cvta.to.shared.u64 t, %1; cvt.u32.u64 %0, t; }" : "=r"(a) : "l"(p));
    return a;
}
__device__ __forceinline__ void cpa16(uint32_t dst, const void* src) {
    asm volatile("cp.async.cg.shared.global [%0], [%1], 16;\n" :: "r"(dst), "l"(src));
}
#define CP_COMMIT()  asm volatile("cp.async.commit_group;\n" ::: "memory")
#define CP_WAIT(n)   asm volatile("cp.async.wait_group %0;\n" :: "n"(n) : "memory")

__device__ __forceinline__ unsigned lds32(uint32_t a) {
    unsigned v;
    asm volatile("ld.shared.b32 %0, [%1];" : "=r"(v) : "r"(a));
    return v;
}

// fp16 MMA: D[16x8] += A[16x16] * B[16x8], fp32 accum
__device__ __forceinline__ void mma_f16(float* c, const unsigned* a, const unsigned* b) {
    asm volatile(
        "mma.sync.aligned.m16n8k16.row.col.f32.f16.f16.f32 "
        "{%0,%1,%2,%3},{%4,%5,%6,%7},{%8,%9},{%0,%1,%2,%3};"
        : "+f"(c[0]), "+f"(c[1]), "+f"(c[2]), "+f"(c[3])
        : "r"(a[0]), "r"(a[1]), "r"(a[2]), "r"(a[3]), "r"(b[0]), "r"(b[1]));
}

// ================ unified FP16 GEMM mainloop ================
// C[M,128-col tile] = A[M,KDIM] @ B[N,KDIM]^T, CTA tile 128x128, BK=32,
// 3-stage cp.async pipeline, 4 warps (2m x 2n), warp tile 64x64.
// EPI==0: fp32 out to g_comb (ld=HD) + bias bv0   (GEMM1, 2D grid)
// EPI==1: fp16 out to g_gates (gate scatter) + per-gate bias (GEMM2, 1D supertiled grid)
#define BK2     32
#define APITCHB 80                 // 64B data + 16B pad: conflict-free fragment LDS
#define STG_BYTES (128 * APITCHB)  // 10240 per operand per stage
#define STAGE_BYTES (2 * STG_BYTES)
#define SM2_TOT (3 * STAGE_BYTES)  // 61440

template <int KDIM, int EPI>
__global__ __launch_bounds__(128)
void gemm_f16(const __half* __restrict__ A0, const __half* __restrict__ B0,
              const float* __restrict__ bv0, const float* __restrict__ bv1,
              const float* __restrict__ bv2, const float* __restrict__ bv3)
{
    extern __shared__ char smem[];
    const uint32_t sb = smem_u32(smem);
    const int tid  = threadIdx.x;
    const int lane = tid & 31;
    const int warp = tid >> 5;
    const int wm   = warp >> 1;     // 0..1
    const int wn   = warp & 1;      // 0..1
    const int gq   = lane >> 2;     // groupID 0..7
    const int tg   = lane & 3;      // thread-in-group

    int m0, n0;
    if (EPI == 0) {
        m0 = blockIdx.y * 128;
        n0 = blockIdx.x * 128;
    } else {
        // supertile decode: 8 n-supers x (64 mblk x 8 nsub) for L2 reuse
        const int bid = blockIdx.x;
        const int nsuper = bid >> 9;
        const int mblk = (bid >> 3) & 63;
        const int nblk = nsuper * 8 + (bid & 7);
        m0 = mblk * 128;
        n0 = nblk * 128;
    }

    const __half* Aptr = A0 + (size_t)m0 * KDIM;
    const __half* Bptr = B0 + (size_t)n0 * KDIM;

    // fill: row = tid (one row per thread), c16 = outer i.
    // smem write start-banks per 8 consecutive lanes = {0,20,8,28,16,4,24,12}*4B
    // -> each 8-lane group covers all 32 banks: conflict-free stores.
    auto fill = [&](int s, int c) {
        const int k0 = c * BK2;
        const uint32_t as = sb + s * STAGE_BYTES;
        const uint32_t bs = as + STG_BYTES;
        const __half* ap = Aptr + (size_t)tid * KDIM + k0;
        const __half* bp = Bptr + (size_t)tid * KDIM + k0;
        const uint32_t arow = as + tid * APITCHB;
        const uint32_t brow = bs + tid * APITCHB;
#pragma unroll
        for (int i = 0; i < 4; i++) {
            cpa16(arow + i * 16, ap + i * 8);
            cpa16(brow + i * 16, bp + i * 8);
        }
        CP_COMMIT();
    };

    float acc[4][8][4];
#pragma unroll
    for (int i = 0; i < 4; i++)
#pragma unroll
        for (int j = 0; j < 8; j++)
#pragma unroll
            for (int k = 0; k < 4; k++) acc[i][j][k] = 0.f;

    fill(0, 0);
    fill(1, 1);

    const uint32_t a_base = (wm * 64 + gq) * APITCHB + tg * 4;
    const uint32_t b_base = (wn * 64 + gq) * APITCHB + tg * 4;

    const int NCH = KDIM / BK2;
    int s = 0;
    for (int c = 0; c < NCH; ++c) {
        if (c < NCH - 1) { CP_WAIT(1); } else { CP_WAIT(0); }
        __syncthreads();

        if (c + 2 < NCH) fill((s + 2) % 3, c + 2);   // overlaps with compute

        const uint32_t as = sb + s * STAGE_BYTES;
        const uint32_t bs = as + STG_BYTES;
#pragma unroll
        for (int kk = 0; kk < 2; ++kk) {
            const uint32_t koff = kk * 32;            // 16 halves
            unsigned af[4][4], bfr[8][2];
#pragma unroll
            for (int mt = 0; mt < 4; ++mt) {
                const uint32_t p = as + a_base + mt * (16 * APITCHB) + koff;
                af[mt][0] = lds32(p);
                af[mt][1] = lds32(p + 8 * APITCHB);
                af[mt][2] = lds32(p + 16);
                af[mt][3] = lds32(p + 8 * APITCHB + 16);
            }
#pragma unroll
            for (int nt = 0; nt < 8; ++nt) {
                const uint32_t p = bs + b_base + nt * (8 * APITCHB) + koff;
                bfr[nt][0] = lds32(p);
                bfr[nt][1] = lds32(p + 16);
            }
#pragma unroll
            for (int mt = 0; mt < 4; ++mt)
#pragma unroll
                for (int nt = 0; nt < 8; ++nt)
                    mma_f16(acc[mt][nt], af[mt], bfr[nt]);
        }
        s = (s + 1) % 3;
        // no trailing sync: the top-of-loop barrier at c+1 orders this
        // iteration's smem reads against fill()'s overwrite of stage s.
    }

    if (EPI == 0) {
        // fp32 out to g_comb [NB, HD] + bias
        float* C = (float*)g_comb;
#pragma unroll
        for (int mt = 0; mt < 4; ++mt) {
            const int row = m0 + wm * 64 + mt * 16 + gq;
#pragma unroll
            for (int nt = 0; nt < 8; ++nt) {
                const int col = n0 + wn * 64 + nt * 8 + 2 * tg;
                const float b0v = bv0[col], b1v = bv0[col + 1];
                float2 v0 = make_float2(acc[mt][nt][0] + b0v, acc[mt][nt][1] + b1v);
                float2 v1 = make_float2(acc[mt][nt][2] + b0v, acc[mt][nt][3] + b1v);
                *(float2*)&C[(size_t)row * HD + col]       = v0;
                *(float2*)&C[(size_t)(row + 8) * HD + col] = v1;
            }
        }
    } else {
        // fp16 out to g_gates; whole CTA lies in one gate (n0 128-aligned)
        const int z = n0 >> 11;
        const int cb0 = n0 & 2047;
        const float* bp = (z == 0) ? bv0 : (z == 1) ? bv1 : (z == 2) ? bv2 : bv3;
        __half* gbase = (__half*)g_gates + (size_t)z * NB * HD;
#pragma unroll
        for (int mt = 0; mt < 4; ++mt) {
            const int row = m0 + wm * 64 + mt * 16 + gq;
#pragma unroll
            for (int nt = 0; nt < 8; ++nt) {
                const int colb = cb0 + wn * 64 + nt * 8 + 2 * tg;
                const float b0v = bp[colb], b1v = bp[colb + 1];
                __half2 h0 = __floats2half2_rn(acc[mt][nt][0] + b0v, acc[mt][nt][1] + b1v);
                __half2 h1 = __floats2half2_rn(acc[mt][nt][2] + b0v, acc[mt][nt][3] + b1v);
                *(__half2*)(gbase + (size_t)row * HD + colb)       = h0;
                *(__half2*)(gbase + (size_t)(row + 8) * HD + colb) = h1;
            }
        }
    }
}

// ================ fp32 -> fp16 converters ================
// fused W_all [8192,4096] from the four gate weights
__global__ __launch_bounds__(256)
void wconv_kernel(const float* __restrict__ Wf, const float* __restrict__ Wi,
                  const float* __restrict__ Wc2, const float* __restrict__ Wo)
{
    const size_t t = (size_t)blockIdx.x * 256 + threadIdx.x;   // one per 8 elems
    const int n  = (int)(t >> 9);
    const int k8 = (int)(t & 511) * 8;
    const float* W = (n < 2048) ? Wf : (n < 4096) ? Wi : (n < 6144) ? Wc2 : Wo;
    const int row = n & 2047;
    const float* src = W + (size_t)row * HD2 + k8;
    float4 v0 = *(const float4*)src;
    float4 v1 = *(const float4*)(src + 4);
    __half2 h[4];
    h[0] = __floats2half2_rn(v0.x, v0.y);
    h[1] = __floats2half2_rn(v0.z, v0.w);
    h[2] = __floats2half2_rn(v1.x, v1.y);
    h[3] = __floats2half2_rn(v1.z, v1.w);
    *(uint4*)((__half*)g_wh + (size_t)n * HD2 + k8) = *(uint4*)h;
}

// generic contiguous fp32 -> fp16 (8 elems/thread)
__global__ __launch_bounds__(256)
void f2h_kernel(const float* __restrict__ s, __half* __restrict__ d, int n8)
{
    const int t = blockIdx.x * 256 + threadIdx.x;
    if (t >= n8) return;
    const float* p = s + (size_t)t * 8;
    float4 v0 = *(const float4*)p;
    float4 v1 = *(const float4*)(p + 4);
    __half2 h[4];
    h[0] = __floats2half2_rn(v0.x, v0.y);
    h[1] = __floats2half2_rn(v0.z, v0.w);
    h[2] = __floats2half2_rn(v1.x, v1.y);
    h[3] = __floats2half2_rn(v1.z, v1.w);
    *(uint4*)(d + (size_t)t * 8) = *(uint4*)h;
}

// ---------------- LN(concat(xp,h)) + tanh -> fp16 g_combh ----------------
__global__ __launch_bounds__(256)
void ln_combined_kernel(const float* __restrict__ h,
                        const float* __restrict__ gln, const float* __restrict__ bln)
{
    __shared__ float sh[16];
    const int row = blockIdx.x;
    const int tid = threadIdx.x;
    const int base = tid * 16;
    const float* src = (base < HD)
        ? ((const float*)g_comb + (long long)row * HD + base)
        : (h + (long long)row * HD + (base - HD));
    float v[16];
#pragma unroll
    for (int i = 0; i < 4; i++) {
        float4 tv = *(const float4*)(src + i * 4);
        v[i * 4 + 0] = tv.x; v[i * 4 + 1] = tv.y; v[i * 4 + 2] = tv.z; v[i * 4 + 3] = tv.w;
    }
    float s = 0.f, ss = 0.f;
#pragma unroll
    for (int i = 0; i < 16; i++) { s += v[i]; ss += v[i] * v[i]; }
#pragma unroll
    for (int o = 16; o; o >>= 1) {
        s  += __shfl_xor_sync(0xffffffffu, s, o);
        ss += __shfl_xor_sync(0xffffffffu, ss, o);
    }
    if ((tid & 31) == 0) { sh[tid >> 5] = s; sh[8 + (tid >> 5)] = ss; }
    __syncthreads();
    s = 0.f; ss = 0.f;
#pragma unroll
    for (int i = 0; i < 8; i++) { s += sh[i]; ss += sh[8 + i]; }
    const float mean = s * (1.f / HD2);
    const float var  = ss * (1.f / HD2) - mean * mean;
    const float rstd = rsqrtf(var + 1e-5f);

    __half2 hv[8];
#pragma unroll
    for (int i = 0; i < 8; i++) {
        const int col = base + i * 2;
        const float a = tanhf((v[i * 2]     - mean) * rstd * gln[col]     + bln[col]);
        const float b = tanhf((v[i * 2 + 1] - mean) * rstd * gln[col + 1] + bln[col + 1]);
        hv[i] = __floats2half2_rn(a, b);
    }
    __half* dst = (__half*)g_combh + (size_t)row * HD2 + base;
    *(uint4*)dst       = *(uint4*)&hv[0];
    *(uint4*)(dst + 8) = *(uint4*)&hv[4];
}

// ---------------- fused gate LNs + cell/hidden update ----------------
__device__ __forceinline__ void load8h(float* v, const __half* p) {
    uint4 u = *(const uint4*)p;
    const __half2* hp = (const __half2*)&u;
#pragma unroll
    for (int i = 0; i < 4; i++) {
        float2 f = __half22float2(hp[i]);
        v[2 * i] = f.x; v[2 * i + 1] = f.y;
    }
}
__device__ __forceinline__ void load8(float* v, const float* p) {
    float4 a = *(const float4*)p;
    float4 b = *(const float4*)(p + 4);
    v[0] = a.x; v[1] = a.y; v[2] = a.z; v[3] = a.w;
    v[4] = b.x; v[5] = b.y; v[6] = b.z; v[7] = b.w;
}
__device__ __forceinline__ void store8(float* p, const float* v) {
    *(float4*)p       = make_float4(v[0], v[1], v[2], v[3]);
    *(float4*)(p + 4) = make_float4(v[4], v[5], v[6], v[7]);
}
__device__ __forceinline__ void sum8(const float* v, float& s, float& ss) {
    s = 0.f; ss = 0.f;
#pragma unroll
    for (int i = 0; i < 8; i++) { s += v[i]; ss += v[i] * v[i]; }
}
__device__ __forceinline__ float sigmoidf_(float x) { return 1.f / (1.f + expf(-x)); }

// batched block-reduction of NV values over 256 threads (8 warps)
template <int NV>
__device__ __forceinline__ void block_reduce(float* sv, float* shm)
{
    const int tid = threadIdx.x;
#pragma unroll
    for (int o = 16; o; o >>= 1)
#pragma unroll
        for (int j = 0; j < NV; j++)
            sv[j] += __shfl_xor_sync(0xffffffffu, sv[j], o);
    if ((tid & 31) == 0) {
#pragma unroll
        for (int j = 0; j < NV; j++) shm[(tid >> 5) * NV + j] = sv[j];
    }
    __syncthreads();
#pragma unroll
    for (int j = 0; j < NV; j++) {
        float t = 0.f;
#pragma unroll
        for (int w = 0; w < 8; w++) t += shm[w * NV + j];
        sv[j] = t;
    }
}

__global__ __launch_bounds__(256)
void final_kernel(const float* __restrict__ c,
                  const float* __restrict__ gf,  const float* __restrict__ bef,
                  const float* __restrict__ gi,  const float* __restrict__ bei,
                  const float* __restrict__ gc2, const float* __restrict__ bec2,
                  const float* __restrict__ go,  const float* __restrict__ beo,
                  const float* __restrict__ gcn, const float* __restrict__ bcn,
                  const float* __restrict__ ghn, const float* __restrict__ bhn,
                  float* __restrict__ out)
{
    __shared__ float sh1[64];
    __shared__ float sh2[16];
    __shared__ float sh3[16];
    const int row = blockIdx.x;
    const int tid = threadIdx.x;
    const int base = tid * 8;
    const long long off = (long long)row * HD + base;

    float vf[8], vi[8], vcc[8], vo[8], vc[8];
    load8h(vf,  (const __half*)g_gates + 0LL * NB * HD + off);
    load8h(vi,  (const __half*)g_gates + 1LL * NB * HD + off);
    load8h(vcc, (const __half*)g_gates + 2LL * NB * HD + off);
    load8h(vo,  (const __half*)g_gates + 3LL * NB * HD + off);
    load8(vc,  c + off);

    // ---- round 1: all four gate LN stats at once ----
    float sv[8];
    sum8(vf,  sv[0], sv[1]);
    sum8(vi,  sv[2], sv[3]);
    sum8(vcc, sv[4], sv[5]);
    sum8(vo,  sv[6], sv[7]);
    block_reduce<8>(sv, sh1);

    float mf = sv[0] * (1.f / HD), rf = rsqrtf(sv[1] * (1.f / HD) - mf * mf + 1e-5f);
    float mi = sv[2] * (1.f / HD), ri = rsqrtf(sv[3] * (1.f / HD) - mi * mi + 1e-5f);
    float mc = sv[4] * (1.f / HD), rc = rsqrtf(sv[5] * (1.f / HD) - mc * mc + 1e-5f);
    float mo = sv[6] * (1.f / HD), ro = rsqrtf(sv[7] * (1.f / HD) - mo * mo + 1e-5f);

#pragma unroll
    for (int i = 0; i < 8; i++) {
        const int col = base + i;
        vf[i]  = sigmoidf_((vf[i]  - mf) * rf * gf[col]  + bef[col]);
        vi[i]  = sigmoidf_((vi[i]  - mi) * ri * gi[col]  + bei[col]);
        vcc[i] = tanhf(    (vcc[i] - mc) * rc * gc2[col] + bec2[col]);
        vo[i]  = sigmoidf_((vo[i]  - mo) * ro * go[col]  + beo[col]);
    }

    // ---- round 2: cell LN ----
    float cell[8];
#pragma unroll
    for (int i = 0; i < 8; i++) cell[i] = vf[i] * vc[i] + vi[i] * vcc[i];
    float sv2[2];
    sum8(cell, sv2[0], sv2[1]);
    block_reduce<2>(sv2, sh2);
    const float mcell = sv2[0] * (1.f / HD);
    const float rcell = rsqrtf(sv2[1] * (1.f / HD) - mcell * mcell + 1e-5f);
#pragma unroll
    for (int i = 0; i < 8; i++)
        cell[i] = (cell[i] - mcell) * rcell * gcn[base + i] + bcn[base + i];
    store8(out + (long long)NB * HD + off, cell);   // next_cell -> out[1]

    // ---- round 3: hidden LN ----
    float hp[8];
#pragma unroll
    for (int i = 0; i < 8; i++) hp[i] = vo[i] * tanhf(cell[i]);
    float sv3[2];
    sum8(hp, sv3[0], sv3[1]);
    block_reduce<2>(sv3, sh3);
    const float mh = sv3[0] * (1.f / HD);
    const float rh = rsqrtf(sv3[1] * (1.f / HD) - mh * mh + 1e-5f);
#pragma unroll
    for (int i = 0; i < 8; i++)
        hp[i] = tanhf((hp[i] - mh) * rh * ghn[base + i] + bhn[base + i]);
    store8(out + off, hp);                          // next_hidden -> out[0]
}

// ---------------- launch ----------------
extern "C" void kernel_launch(void* const* d_in, const int* in_sizes, int n_in,
                              void* d_out, int out_size)
{
    const float* x      = (const float*)d_in[0];
    const float* h      = (const float*)d_in[1];
    const float* c      = (const float*)d_in[2];
    const float* W_proj = (const float*)d_in[3];
    const float* b_proj = (const float*)d_in[4];
    const float* g_ln   = (const float*)d_in[5];
    const float* b_ln   = (const float*)d_in[6];
    const float* g_cn   = (const float*)d_in[7];
    const float* b_cn   = (const float*)d_in[8];
    const float* g_hn   = (const float*)d_in[9];
    const float* b_hn   = (const float*)d_in[10];
    const float* W_f    = (const float*)d_in[11];
    const float* b_f    = (const float*)d_in[12];
    const float* gq_f   = (const float*)d_in[13];
    const float* be_f   = (const float*)d_in[14];
    const float* W_i    = (const float*)d_in[15];
    const float* b_i    = (const float*)d_in[16];
    const float* gq_i   = (const float*)d_in[17];
    const float* be_i   = (const float*)d_in[18];
    const float* W_c2   = (const float*)d_in[19];
    const float* b_c2   = (const float*)d_in[20];
    const float* gq_c2  = (const float*)d_in[21];
    const float* be_c2  = (const float*)d_in[22];
    const float* W_o    = (const float*)d_in[23];
    const float* b_o    = (const float*)d_in[24];
    const float* gq_o   = (const float*)d_in[25];
    const float* be_o   = (const float*)d_in[26];
    float* out = (float*)d_out;

    __half* xh  = nullptr;  cudaGetSymbolAddress((void**)&xh,  g_xh);
    __half* wph = nullptr;  cudaGetSymbolAddress((void**)&wph, g_wph);
    __half* wh  = nullptr;  cudaGetSymbolAddress((void**)&wh,  g_wh);
    __half* cbh = nullptr;  cudaGetSymbolAddress((void**)&cbh, g_combh);

    dim3 blk(256);

    // 0) fp32 -> fp16 conversions: W_all (fused), x, W_proj
    wconv_kernel<<<16384, blk>>>(W_f, W_i, W_c2, W_o);
    f2h_kernel<<<(NB * KCIN / 8 + 255) / 256, blk>>>(x, xh, NB * KCIN / 8);
    f2h_kernel<<<(HD * KCIN / 8 + 255) / 256, blk>>>(W_proj, wph, HD * KCIN / 8);

    // 1) xp = x @ W_proj^T + b_proj -> g_comb [8192,2048] fp32 (fp16 MMA)
    cudaFuncSetAttribute(gemm_f16<KCIN, 0>, cudaFuncAttributeMaxDynamicSharedMemorySize, SM2_TOT);
    gemm_f16<KCIN, 0><<<dim3(HD / 128, NB / 128), 128, SM2_TOT>>>(
        xh, wph, b_proj, nullptr, nullptr, nullptr);

    // 2) combined = fp16(tanh(LN(concat(xp, h)))) -> g_combh [8192,4096]
    ln_combined_kernel<<<NB, blk>>>(h, g_ln, b_ln);

    // 3) gates = combined @ W_all^T + b  -> g_gates (fp16)
    cudaFuncSetAttribute(gemm_f16<HD2, 1>, cudaFuncAttributeMaxDynamicSharedMemorySize, SM2_TOT);
    gemm_f16<HD2, 1><<<4096, 128, SM2_TOT>>>(cbh, wh, b_f, b_i, b_c2, b_o);

    // 4) fused gate LNs + activations + cell/hidden LNs -> out[2,B,H]
    final_kernel<<<NB, blk>>>(c,
                              gq_f, be_f, gq_i, be_i, gq_c2, be_c2, gq_o, be_o,
                              g_cn, b_cn, g_hn, b_hn, out);
}

// round 16
// speedup vs baseline: 1.4058x; 1.4058x over previous
#include <cuda_runtime.h>
#include <cuda_fp16.h>
#include <cstdint>

// Problem dims (fixed by the dataset)
#define NB   8192   // batch
#define KCIN 512    // in_channels
#define HD   2048   // hidden
#define HD2  4096   // 2*hidden

// -------- scratch (device globals: allocation-free rule) --------
__device__ float  g_comb[NB * HD];            // 67 MB: xp (fp32, GEMM1 out / LN in)
__device__ __half g_combh[(size_t)NB * HD2];  // 67 MB: fp16 tanh(LN(concat))
__device__ __half g_wh[(size_t)8192 * HD2];   // 67 MB: fp16 fused W_all [8192,4096]
__device__ __half g_xh[(size_t)NB * KCIN];    // 8 MB:  fp16 x
__device__ __half g_wph[(size_t)HD * KCIN];   // 2 MB:  fp16 W_proj
__device__ __half g_gates[4LL * NB * HD];     // 134 MB: f,i,c2,o pre-activations (fp16)

// ================= small helpers =================
__device__ __forceinline__ uint32_t smem_u32(const void* p) {
    uint32_t a;
    asm("{ .reg .u64 t; cvta.to.shared.u64 t, %1; cvt.u32.u64 %0, t; }" : "=r"(a) : "l"(p));
    return a;
}
__device__ __forceinline__ void cpa16(uint32_t dst, const void* src) {
    asm volatile("cp.async.cg.shared.global [%0], [%1], 16;\n" :: "r"(dst), "l"(src));
}
#define CP_COMMIT()  asm volatile("cp.async.commit_group;\n" ::: "memory")
#define CP_WAIT(n)   asm volatile("cp.async.wait_group %0;\n" :: "n"(n) : "memory")

__device__ __forceinline__ unsigned lds32(uint32_t a) {
    unsigned v;
    asm volatile("ld.shared.b32 %0, [%1];" : "=r"(v) : "r"(a));
    return v;
}

// fp16 MMA: D[16x8] += A[16x16] * B[16x8], fp32 accum
__device__ __forceinline__ void mma_f16(float* c, const unsigned* a, const unsigned* b) {
    asm volatile(
        "mma.sync.aligned.m16n8k16.row.col.f32.f16.f16.f32 "
        "{%0,%1,%2,%3},{%4,%5,%6,%7},{%8,%9},{%0,%1,%2,%3};"
        : "+f"(c[0]), "+f"(c[1]), "+f"(c[2]), "+f"(c[3])
        : "r"(a[0]), "r"(a[1]), "r"(a[2]), "r"(a[3]), "r"(b[0]), "r"(b[1]));
}

// ================ unified FP16 GEMM mainloop ================
// C[M,128-col tile] = A[M,KDIM] @ B[N,KDIM]^T, CTA tile 128x128, BK=32,
// 3-stage cp.async pipeline, 4 warps (2m x 2n), warp tile 64x64.
// EPI==0: fp32 out to g_comb (ld=HD) + bias bv0   (GEMM1, 2D grid)
// EPI==1: fp16 out to g_gates (gate scatter) + per-gate bias (GEMM2, 1D supertiled grid)
#define BK2     32
#define APITCHB 80                 // 64B data + 16B pad: conflict-free fragment LDS
#define STG_BYTES (128 * APITCHB)  // 10240 per operand per stage
#define STAGE_BYTES (2 * STG_BYTES)
#define SM2_TOT (3 * STAGE_BYTES)  // 61440

template <int KDIM, int EPI>
__global__ __launch_bounds__(128, 3)
void gemm_f16(const __half* __restrict__ A0, const __half* __restrict__ B0,
              const float* __restrict__ bv0, const float* __restrict__ bv1,
              const float* __restrict__ bv2, const float* __restrict__ bv3)
{
    extern __shared__ char smem[];
    const uint32_t sb = smem_u32(smem);
    const int tid  = threadIdx.x;
    const int lane = tid & 31;
    const int warp = tid >> 5;
    const int wm   = warp >> 1;     // 0..1
    const int wn   = warp & 1;      // 0..1
    const int gq   = lane >> 2;     // groupID 0..7
    const int tg   = lane & 3;      // thread-in-group

    int m0, n0;
    if (EPI == 0) {
        m0 = blockIdx.y * 128;
        n0 = blockIdx.x * 128;
    } else {
        // supertile decode: 8 n-supers x (64 mblk x 8 nsub) for L2 reuse
        const int bid = blockIdx.x;
        const int nsuper = bid >> 9;
        const int mblk = (bid >> 3) & 63;
        const int nblk = nsuper * 8 + (bid & 7);
        m0 = mblk * 128;
        n0 = nblk * 128;
    }

    const __half* Aptr = A0 + (size_t)m0 * KDIM;
    const __half* Bptr = B0 + (size_t)n0 * KDIM;

    // fill (round-12 mapping — coalesced): 4 consecutive threads cover one
    // row's 64B (4 x 16B granules); warp = 8 rows x 64B contiguous segments.
    auto fill = [&](int s, int c) {
        const int k0 = c * BK2;
        const uint32_t as = sb + s * STAGE_BYTES;
        const uint32_t bs = as + STG_BYTES;
#pragma unroll
        for (int i = 0; i < 4; i++) {
            const int g = tid + i * 128;     // 0..511
            const int row = g >> 2, c16 = g & 3;
            cpa16(as + row * APITCHB + c16 * 16,
                  Aptr + (size_t)row * KDIM + k0 + c16 * 8);
            cpa16(bs + row * APITCHB + c16 * 16,
                  Bptr + (size_t)row * KDIM + k0 + c16 * 8);
        }
        CP_COMMIT();
    };

    float acc[4][8][4];
#pragma unroll
    for (int i = 0; i < 4; i++)
#pragma unroll
        for (int j = 0; j < 8; j++)
#pragma unroll
            for (int k = 0; k < 4; k++) acc[i][j][k] = 0.f;

    fill(0, 0);
    fill(1, 1);

    const uint32_t a_base = (wm * 64 + gq) * APITCHB + tg * 4;
    const uint32_t b_base = (wn * 64 + gq) * APITCHB + tg * 4;

    const int NCH = KDIM / BK2;
    int s = 0;
    for (int c = 0; c < NCH; ++c) {
        if (c < NCH - 1) { CP_WAIT(1); } else { CP_WAIT(0); }
        __syncthreads();

        if (c + 2 < NCH) fill((s + 2) % 3, c + 2);   // overlaps with compute

        const uint32_t as = sb + s * STAGE_BYTES;
        const uint32_t bs = as + STG_BYTES;
#pragma unroll
        for (int kk = 0; kk < 2; ++kk) {
            const uint32_t koff = kk * 32;            // 16 halves
            unsigned af[4][4], bfr[8][2];
#pragma unroll
            for (int mt = 0; mt < 4; ++mt) {
                const uint32_t p = as + a_base + mt * (16 * APITCHB) + koff;
                af[mt][0] = lds32(p);
                af[mt][1] = lds32(p + 8 * APITCHB);
                af[mt][2] = lds32(p + 16);
                af[mt][3] = lds32(p + 8 * APITCHB + 16);
            }
#pragma unroll
            for (int nt = 0; nt < 8; ++nt) {
                const uint32_t p = bs + b_base + nt * (8 * APITCHB) + koff;
                bfr[nt][0] = lds32(p);
                bfr[nt][1] = lds32(p + 16);
            }
#pragma unroll
            for (int mt = 0; mt < 4; ++mt)
#pragma unroll
                for (int nt = 0; nt < 8; ++nt)
                    mma_f16(acc[mt][nt], af[mt], bfr[nt]);
        }
        s = (s + 1) % 3;
        // no trailing sync: the top-of-loop barrier at c+1 orders this
        // iteration's smem reads against fill()'s overwrite of stage s.
    }

    if (EPI == 0) {
        // fp32 out to g_comb [NB, HD] + bias
        float* C = (float*)g_comb;
#pragma unroll
        for (int mt = 0; mt < 4; ++mt) {
            const int row = m0 + wm * 64 + mt * 16 + gq;
#pragma unroll
            for (int nt = 0; nt < 8; ++nt) {
                const int col = n0 + wn * 64 + nt * 8 + 2 * tg;
                const float b0v = bv0[col], b1v = bv0[col + 1];
                float2 v0 = make_float2(acc[mt][nt][0] + b0v, acc[mt][nt][1] + b1v);
                float2 v1 = make_float2(acc[mt][nt][2] + b0v, acc[mt][nt][3] + b1v);
                *(float2*)&C[(size_t)row * HD + col]       = v0;
                *(float2*)&C[(size_t)(row + 8) * HD + col] = v1;
            }
        }
    } else {
        // fp16 out to g_gates; whole CTA lies in one gate (n0 128-aligned)
        const int z = n0 >> 11;
        const int cb0 = n0 & 2047;
        const float* bp = (z == 0) ? bv0 : (z == 1) ? bv1 : (z == 2) ? bv2 : bv3;
        __half* gbase = (__half*)g_gates + (size_t)z * NB * HD;
#pragma unroll
        for (int mt = 0; mt < 4; ++mt) {
            const int row = m0 + wm * 64 + mt * 16 + gq;
#pragma unroll
            for (int nt = 0; nt < 8; ++nt) {
                const int colb = cb0 + wn * 64 + nt * 8 + 2 * tg;
                const float b0v = bp[colb], b1v = bp[colb + 1];
                __half2 h0 = __floats2half2_rn(acc[mt][nt][0] + b0v, acc[mt][nt][1] + b1v);
                __half2 h1 = __floats2half2_rn(acc[mt][nt][2] + b0v, acc[mt][nt][3] + b1v);
                *(__half2*)(gbase + (size_t)row * HD + colb)       = h0;
                *(__half2*)(gbase + (size_t)(row + 8) * HD + colb) = h1;
            }
        }
    }
}

// ================ fp32 -> fp16 converters ================
// fused W_all [8192,4096] from the four gate weights
__global__ __launch_bounds__(256)
void wconv_kernel(const float* __restrict__ Wf, const float* __restrict__ Wi,
                  const float* __restrict__ Wc2, const float* __restrict__ Wo)
{
    const size_t t = (size_t)blockIdx.x * 256 + threadIdx.x;   // one per 8 elems
    const int n  = (int)(t >> 9);
    const int k8 = (int)(t & 511) * 8;
    const float* W = (n < 2048) ? Wf : (n < 4096) ? Wi : (n < 6144) ? Wc2 : Wo;
    const int row = n & 2047;
    const float* src = W + (size_t)row * HD2 + k8;
    float4 v0 = *(const float4*)src;
    float4 v1 = *(const float4*)(src + 4);
    __half2 h[4];
    h[0] = __floats2half2_rn(v0.x, v0.y);
    h[1] = __floats2half2_rn(v0.z, v0.w);
    h[2] = __floats2half2_rn(v1.x, v1.y);
    h[3] = __floats2half2_rn(v1.z, v1.w);
    *(uint4*)((__half*)g_wh + (size_t)n * HD2 + k8) = *(uint4*)h;
}

// generic contiguous fp32 -> fp16 (8 elems/thread)
__global__ __launch_bounds__(256)
void f2h_kernel(const float* __restrict__ s, __half* __restrict__ d, int n8)
{
    const int t = blockIdx.x * 256 + threadIdx.x;
    if (t >= n8) return;
    const float* p = s + (size_t)t * 8;
    float4 v0 = *(const float4*)p;
    float4 v1 = *(const float4*)(p + 4);
    __half2 h[4];
    h[0] = __floats2half2_rn(v0.x, v0.y);
    h[1] = __floats2half2_rn(v0.z, v0.w);
    h[2] = __floats2half2_rn(v1.x, v1.y);
    h[3] = __floats2half2_rn(v1.z, v1.w);
    *(uint4*)(d + (size_t)t * 8) = *(uint4*)h;
}

// ---------------- LN(concat(xp,h)) + tanh -> fp16 g_combh ----------------
__global__ __launch_bounds__(256)
void ln_combined_kernel(const float* __restrict__ h,
                        const float* __restrict__ gln, const float* __restrict__ bln)
{
    __shared__ float sh[16];
    const int row = blockIdx.x;
    const int tid = threadIdx.x;
    const int base = tid * 16;
    const float* src = (base < HD)
        ? ((const float*)g_comb + (long long)row * HD + base)
        : (h + (long long)row * HD + (base - HD));
    float v[16];
#pragma unroll
    for (int i = 0; i < 4; i++) {
        float4 tv = *(const float4*)(src + i * 4);
        v[i * 4 + 0] = tv.x; v[i * 4 + 1] = tv.y; v[i * 4 + 2] = tv.z; v[i * 4 + 3] = tv.w;
    }
    float s = 0.f, ss = 0.f;
#pragma unroll
    for (int i = 0; i < 16; i++) { s += v[i]; ss += v[i] * v[i]; }
#pragma unroll
    for (int o = 16; o; o >>= 1) {
        s  += __shfl_xor_sync(0xffffffffu, s, o);
        ss += __shfl_xor_sync(0xffffffffu, ss, o);
    }
    if ((tid & 31) == 0) { sh[tid >> 5] = s; sh[8 + (tid >> 5)] = ss; }
    __syncthreads();
    s = 0.f; ss = 0.f;
#pragma unroll
    for (int i = 0; i < 8; i++) { s += sh[i]; ss += sh[8 + i]; }
    const float mean = s * (1.f / HD2);
    const float var  = ss * (1.f / HD2) - mean * mean;
    const float rstd = rsqrtf(var + 1e-5f);

    __half2 hv[8];
#pragma unroll
    for (int i = 0; i < 8; i++) {
        const int col = base + i * 2;
        const float a = tanhf((v[i * 2]     - mean) * rstd * gln[col]     + bln[col]);
        const float b = tanhf((v[i * 2 + 1] - mean) * rstd * gln[col + 1] + bln[col + 1]);
        hv[i] = __floats2half2_rn(a, b);
    }
    __half* dst = (__half*)g_combh + (size_t)row * HD2 + base;
    *(uint4*)dst       = *(uint4*)&hv[0];
    *(uint4*)(dst + 8) = *(uint4*)&hv[4];
}

// ---------------- fused gate LNs + cell/hidden update ----------------
__device__ __forceinline__ void load8h(float* v, const __half* p) {
    uint4 u = *(const uint4*)p;
    const __half2* hp = (const __half2*)&u;
#pragma unroll
    for (int i = 0; i < 4; i++) {
        float2 f = __half22float2(hp[i]);
        v[2 * i] = f.x; v[2 * i + 1] = f.y;
    }
}
__device__ __forceinline__ void load8(float* v, const float* p) {
    float4 a = *(const float4*)p;
    float4 b = *(const float4*)(p + 4);
    v[0] = a.x; v[1] = a.y; v[2] = a.z; v[3] = a.w;
    v[4] = b.x; v[5] = b.y; v[6] = b.z; v[7] = b.w;
}
__device__ __forceinline__ void store8(float* p, const float* v) {
    *(float4*)p       = make_float4(v[0], v[1], v[2], v[3]);
    *(float4*)(p + 4) = make_float4(v[4], v[5], v[6], v[7]);
}
__device__ __forceinline__ void sum8(const float* v, float& s, float& ss) {
    s = 0.f; ss = 0.f;
#pragma unroll
    for (int i = 0; i < 8; i++) { s += v[i]; ss += v[i] * v[i]; }
}
__device__ __forceinline__ float sigmoidf_(float x) { return 1.f / (1.f + expf(-x)); }

// batched block-reduction of NV values over 256 threads (8 warps)
template <int NV>
__device__ __forceinline__ void block_reduce(float* sv, float* shm)
{
    const int tid = threadIdx.x;
#pragma unroll
    for (int o = 16; o; o >>= 1)
#pragma unroll
        for (int j = 0; j < NV; j++)
            sv[j] += __shfl_xor_sync(0xffffffffu, sv[j], o);
    if ((tid & 31) == 0) {
#pragma unroll
        for (int j = 0; j < NV; j++) shm[(tid >> 5) * NV + j] = sv[j];
    }
    __syncthreads();
#pragma unroll
    for (int j = 0; j < NV; j++) {
        float t = 0.f;
#pragma unroll
        for (int w = 0; w < 8; w++) t += shm[w * NV + j];
        sv[j] = t;
    }
}

__global__ __launch_bounds__(256)
void final_kernel(const float* __restrict__ c,
                  const float* __restrict__ gf,  const float* __restrict__ bef,
                  const float* __restrict__ gi,  const float* __restrict__ bei,
                  const float* __restrict__ gc2, const float* __restrict__ bec2,
                  const float* __restrict__ go,  const float* __restrict__ beo,
                  const float* __restrict__ gcn, const float* __restrict__ bcn,
                  const float* __restrict__ ghn, const float* __restrict__ bhn,
                  float* __restrict__ out)
{
    __shared__ float sh1[64];
    __shared__ float sh2[16];
    __shared__ float sh3[16];
    const int row = blockIdx.x;
    const int tid = threadIdx.x;
    const int base = tid * 8;
    const long long off = (long long)row * HD + base;

    float vf[8], vi[8], vcc[8], vo[8], vc[8];
    load8h(vf,  (const __half*)g_gates + 0LL * NB * HD + off);
    load8h(vi,  (const __half*)g_gates + 1LL * NB * HD + off);
    load8h(vcc, (const __half*)g_gates + 2LL * NB * HD + off);
    load8h(vo,  (const __half*)g_gates + 3LL * NB * HD + off);
    load8(vc,  c + off);

    // ---- round 1: all four gate LN stats at once ----
    float sv[8];
    sum8(vf,  sv[0], sv[1]);
    sum8(vi,  sv[2], sv[3]);
    sum8(vcc, sv[4], sv[5]);
    sum8(vo,  sv[6], sv[7]);
    block_reduce<8>(sv, sh1);

    float mf = sv[0] * (1.f / HD), rf = rsqrtf(sv[1] * (1.f / HD) - mf * mf + 1e-5f);
    float mi = sv[2] * (1.f / HD), ri = rsqrtf(sv[3] * (1.f / HD) - mi * mi + 1e-5f);
    float mc = sv[4] * (1.f / HD), rc = rsqrtf(sv[5] * (1.f / HD) - mc * mc + 1e-5f);
    float mo = sv[6] * (1.f / HD), ro = rsqrtf(sv[7] * (1.f / HD) - mo * mo + 1e-5f);

#pragma unroll
    for (int i = 0; i < 8; i++) {
        const int col = base + i;
        vf[i]  = sigmoidf_((vf[i]  - mf) * rf * gf[col]  + bef[col]);
        vi[i]  = sigmoidf_((vi[i]  - mi) * ri * gi[col]  + bei[col]);
        vcc[i] = tanhf(    (vcc[i] - mc) * rc * gc2[col] + bec2[col]);
        vo[i]  = sigmoidf_((vo[i]  - mo) * ro * go[col]  + beo[col]);
    }

    // ---- round 2: cell LN ----
    float cell[8];
#pragma unroll
    for (int i = 0; i < 8; i++) cell[i] = vf[i] * vc[i] + vi[i] * vcc[i];
    float sv2[2];
    sum8(cell, sv2[0], sv2[1]);
    block_reduce<2>(sv2, sh2);
    const float mcell = sv2[0] * (1.f / HD);
    const float rcell = rsqrtf(sv2[1] * (1.f / HD) - mcell * mcell + 1e-5f);
#pragma unroll
    for (int i = 0; i < 8; i++)
        cell[i] = (cell[i] - mcell) * rcell * gcn[base + i] + bcn[base + i];
    store8(out + (long long)NB * HD + off, cell);   // next_cell -> out[1]

    // ---- round 3: hidden LN ----
    float hp[8];
#pragma unroll
    for (int i = 0; i < 8; i++) hp[i] = vo[i] * tanhf(cell[i]);
    float sv3[2];
    sum8(hp, sv3[0], sv3[1]);
    block_reduce<2>(sv3, sh3);
    const float mh = sv3[0] * (1.f / HD);
    const float rh = rsqrtf(sv3[1] * (1.f / HD) - mh * mh + 1e-5f);
#pragma unroll
    for (int i = 0; i < 8; i++)
        hp[i] = tanhf((hp[i] - mh) * rh * ghn[base + i] + bhn[base + i]);
    store8(out + off, hp);                          // next_hidden -> out[0]
}

// ---------------- launch ----------------
extern "C" void kernel_launch(void* const* d_in, const int* in_sizes, int n_in,
                              void* d_out, int out_size)
{
    const float* x      = (const float*)d_in[0];
    const float* h      = (const float*)d_in[1];
    const float* c      = (const float*)d_in[2];
    const float* W_proj = (const float*)d_in[3];
    const float* b_proj = (const float*)d_in[4];
    const float* g_ln   = (const float*)d_in[5];
    const float* b_ln   = (const float*)d_in[6];
    const float* g_cn   = (const float*)d_in[7];
    const float* b_cn   = (const float*)d_in[8];
    const float* g_hn   = (const float*)d_in[9];
    const float* b_hn   = (const float*)d_in[10];
    const float* W_f    = (const float*)d_in[11];
    const float* b_f    = (const float*)d_in[12];
    const float* gq_f   = (const float*)d_in[13];
    const float* be_f   = (const float*)d_in[14];
    const float* W_i    = (const float*)d_in[15];
    const float* b_i    = (const float*)d_in[16];
    const float* gq_i   = (const float*)d_in[17];
    const float* be_i   = (const float*)d_in[18];
    const float* W_c2   = (const float*)d_in[19];
    const float* b_c2   = (const float*)d_in[20];
    const float* gq_c2  = (const float*)d_in[21];
    const float* be_c2  = (const float*)d_in[22];
    const float* W_o    = (const float*)d_in[23];
    const float* b_o    = (const float*)d_in[24];
    const float* gq_o   = (const float*)d_in[25];
    const float* be_o   = (const float*)d_in[26];
    float* out = (float*)d_out;

    __half* xh  = nullptr;  cudaGetSymbolAddress((void**)&xh,  g_xh);
    __half* wph = nullptr;  cudaGetSymbolAddress((void**)&wph, g_wph);
    __half* wh  = nullptr;  cudaGetSymbolAddress((void**)&wh,  g_wh);
    __half* cbh = nullptr;  cudaGetSymbolAddress((void**)&cbh, g_combh);

    dim3 blk(256);

    // 0) fp32 -> fp16 conversions: W_all (fused), x, W_proj
    wconv_kernel<<<16384, blk>>>(W_f, W_i, W_c2, W_o);
    f2h_kernel<<<(NB * KCIN / 8 + 255) / 256, blk>>>(x, xh, NB * KCIN / 8);
    f2h_kernel<<<(HD * KCIN / 8 + 255) / 256, blk>>>(W_proj, wph, HD * KCIN / 8);

    // 1) xp = x @ W_proj^T + b_proj -> g_comb [8192,2048] fp32 (fp16 MMA)
    cudaFuncSetAttribute(gemm_f16<KCIN, 0>, cudaFuncAttributeMaxDynamicSharedMemorySize, SM2_TOT);
    gemm_f16<KCIN, 0><<<dim3(HD / 128, NB / 128), 128, SM2_TOT>>>(
        xh, wph, b_proj, nullptr, nullptr, nullptr);

    // 2) combined = fp16(tanh(LN(concat(xp, h)))) -> g_combh [8192,4096]
    ln_combined_kernel<<<NB, blk>>>(h, g_ln, b_ln);

    // 3) gates = combined @ W_all^T + b  -> g_gates (fp16)
    cudaFuncSetAttribute(gemm_f16<HD2, 1>, cudaFuncAttributeMaxDynamicSharedMemorySize, SM2_TOT);
    gemm_f16<HD2, 1><<<4096, 128, SM2_TOT>>>(cbh, wh, b_f, b_i, b_c2, b_o);

    // 4) fused gate LNs + activations + cell/hidden LNs -> out[2,B,H]
    final_kernel<<<NB, blk>>>(c,
                              gq_f, be_f, gq_i, be_i, gq_c2, be_c2, gq_o, be_o,
                              g_cn, b_cn, g_hn, b_hn, out);
}